// round 1
// baseline (speedup 1.0000x reference)
#include <cuda_runtime.h>

#define NN 784
#define GRID 28
#define MAXB 64
#define MAXD2 1459   // d2 in [0, 27^2+27^2=1458]

// Scratch (device globals — no allocations allowed)
__device__ unsigned short g_sort_idx[NN * NN];     // [i][rank] -> neighbor index
__device__ float g_fvals[2 * MAXB * NN];           // [g][m][i] dtm values
__device__ float g_pB[4 * MAXB * NN];              // per-task birth VALUES
__device__ float g_pD[4 * MAXB * NN];              // per-task death VALUES

__constant__ int c_dxs[8] = {-1, 1, 0, 0, -1, -1, 1, 1};
__constant__ int c_dys[8] = {0, 0, -1, 1, -1, 1, -1, 1};

// ---------------------------------------------------------------------------
// Kernel A: stable argsort of squared grid distances per point (counting sort)
// ---------------------------------------------------------------------------
__global__ void build_sort_table_kernel() {
    int i = blockIdx.x;
    int xi = i / GRID, yi = i % GRID;
    __shared__ unsigned int hist[MAXD2];
    __shared__ unsigned short d2a[NN];
    __shared__ unsigned int wsum[8];
    int tid = threadIdx.x;
    int lane = tid & 31, warp = tid >> 5;

    for (int t = tid; t < MAXD2; t += 256) hist[t] = 0u;
    __syncthreads();
    for (int j = tid; j < NN; j += 256) {
        int dx = j / GRID - xi, dy = j % GRID - yi;
        int d2 = dx * dx + dy * dy;
        d2a[j] = (unsigned short)d2;
        atomicAdd(&hist[d2], 1u);
    }
    __syncthreads();

    // exclusive scan of hist[0..1458] (6 entries per thread, 256 threads)
    unsigned int lv[6];
    unsigned int s = 0u;
    int base = tid * 6;
#pragma unroll
    for (int c = 0; c < 6; c++) {
        unsigned int v = (base + c < MAXD2) ? hist[base + c] : 0u;
        lv[c] = s;
        s += v;
    }
    unsigned int inc = s;
#pragma unroll
    for (int off = 1; off < 32; off <<= 1) {
        unsigned int t = __shfl_up_sync(0xFFFFFFFFu, inc, off);
        if (lane >= off) inc += t;
    }
    if (lane == 31) wsum[warp] = inc;
    __syncthreads();
    if (tid == 0) {
        unsigned int a = 0u;
        for (int w = 0; w < 8; w++) { unsigned int t = wsum[w]; wsum[w] = a; a += t; }
    }
    __syncthreads();
    unsigned int off0 = wsum[warp] + (inc - s);
    __syncthreads();  // all reads of hist done before overwrite
#pragma unroll
    for (int c = 0; c < 6; c++)
        if (base + c < MAXD2) hist[base + c] = off0 + lv[c];
    __syncthreads();

    // Stable scatter: warps serialized in ascending-j order
    for (int gq = 0; gq < 25; gq++) {
        if (warp == (gq & 7)) {
            int j = gq * 32 + lane;
            bool valid = (j < NN);
            unsigned int key = valid ? (unsigned int)d2a[j] : 0xFFFFu;
            unsigned int mk = __match_any_sync(0xFFFFFFFFu, key);
            int leader = __ffs(mk) - 1;
            int pre = __popc(mk & ((1u << lane) - 1u));
            unsigned int b0 = 0u;
            if (lane == leader && valid) b0 = atomicAdd(&hist[key], (unsigned int)__popc(mk));
            b0 = __shfl_sync(0xFFFFFFFFu, b0, leader);
            if (valid) g_sort_idx[i * NN + b0 + pre] = (unsigned short)j;
        }
        __syncthreads();
    }
}

// ---------------------------------------------------------------------------
// Kernel B: DTM for both m0 values in a single pass. Block per image.
// ---------------------------------------------------------------------------
__global__ void dtm_kernel(const float* __restrict__ x) {
    int m = blockIdx.x;
    __shared__ float img[NN];
    __shared__ float red[8];
    int tid = threadIdx.x;
    int lane = tid & 31, warp = tid >> 5;

    float ps = 0.f;
    for (int j = tid; j < NN; j += 256) {
        float v = x[m * NN + j];
        img[j] = v;
        ps += v;
    }
#pragma unroll
    for (int off = 16; off; off >>= 1) ps += __shfl_xor_sync(0xFFFFFFFFu, ps, off);
    if (lane == 0) red[warp] = ps;
    __syncthreads();
    float S = 0.f;
#pragma unroll
    for (int w = 0; w < 8; w++) S += red[w];
    float bound1 = 0.05f * S;
    float bound2 = 0.2f * S;

    for (int i = warp; i < NN; i += 8) {
        int xi = i / GRID, yi = i % GRID;
        float acc1 = 0.f, acc2 = 0.f, running = 0.f;
        for (int c = 0; c < NN; c += 32) {
            int j = c + lane;
            float w = 0.f, fd2 = 0.f;
            if (j < NN) {
                int idx = (int)g_sort_idx[i * NN + j];
                w = img[idx];
                int dx = idx / GRID - xi, dy = idx % GRID - yi;
                fd2 = (float)(dx * dx + dy * dy);
            }
            float cs = w;
#pragma unroll
            for (int off = 1; off < 32; off <<= 1) {
                float t = __shfl_up_sync(0xFFFFFFFFu, cs, off);
                if (lane >= off) cs += t;
            }
            float cumBefore = running + cs - w;
            float e1 = fminf(fmaxf(bound1 - cumBefore, 0.f), w);
            float e2 = fminf(fmaxf(bound2 - cumBefore, 0.f), w);
            acc1 += e1 * fd2;
            acc2 += e2 * fd2;
            running += __shfl_sync(0xFFFFFFFFu, cs, 31);
            if (running >= bound2) break;  // all further eff are exactly 0
        }
#pragma unroll
        for (int off = 16; off; off >>= 1) {
            acc1 += __shfl_xor_sync(0xFFFFFFFFu, acc1, off);
            acc2 += __shfl_xor_sync(0xFFFFFFFFu, acc2, off);
        }
        if (lane == 0) {
            g_fvals[(0 * MAXB + m) * NN + i] = sqrtf(acc1 / bound1);
            g_fvals[(1 * MAXB + m) * NN + i] = sqrtf(acc2 / bound2);
        }
    }
}

// ---------------------------------------------------------------------------
// Kernel C: per-task stable sort (bitonic, 64-bit packed keys) + union-find.
// task = ((m*2+g)*2+dir). Outputs birth/death VALUES (pair order irrelevant).
// ---------------------------------------------------------------------------
__global__ void pairs_kernel() {
    int task = blockIdx.x;
    int dir = task & 1;
    int g = (task >> 1) & 1;
    int m = task >> 2;

    __shared__ float vals[NN];
    __shared__ unsigned long long keys[1024];
    __shared__ unsigned short order_[NN], pos_[NN], parent_[NN], birthp_[NN];
    __shared__ unsigned short sroots[8];
    int tid = threadIdx.x;

    for (int j = tid; j < NN; j += 256) {
        float v = g_fvals[(g * MAXB + m) * NN + j];
        vals[j] = v;
        float kf = dir ? -v : v;  // dir1: superlevel via -x
        unsigned int u = __float_as_uint(kf);
        u = (u & 0x80000000u) ? ~u : (u | 0x80000000u);  // sortable transform
        keys[j] = ((unsigned long long)u << 32) | (unsigned int)j;  // stable ties by j
    }
    for (int j = NN + tid; j < 1024; j += 256) keys[j] = ~0ULL;
    __syncthreads();

    // bitonic sort of 1024 keys
    for (int k = 2; k <= 1024; k <<= 1) {
        for (int jj = k >> 1; jj > 0; jj >>= 1) {
            for (int i = tid; i < 1024; i += 256) {
                int ixj = i ^ jj;
                if (ixj > i) {
                    unsigned long long a = keys[i], b = keys[ixj];
                    bool up = ((i & k) == 0);
                    if ((a > b) == up) { keys[i] = b; keys[ixj] = a; }
                }
            }
            __syncthreads();
        }
    }

    for (int r = tid; r < NN; r += 256) {
        int j = (int)(unsigned int)keys[r];
        order_[r] = (unsigned short)j;
        pos_[j] = (unsigned short)r;
        parent_[j] = (unsigned short)j;
        birthp_[j] = (unsigned short)r;  // birth pos of singleton = own pos
    }
    float* pB = g_pB + task * NN;
    float* pD = g_pD + task * NN;
    for (int j = tid; j < NN; j += 256) { pB[j] = 0.f; pD[j] = 0.f; }  // zero slots -> tent 0
    __syncthreads();

    if (tid >= 32) return;  // warp 0 does the union-find
    int lane = tid;
    int nn = dir ? 8 : 4;
    volatile unsigned short* par = parent_;
    int k = 0;

    for (int r = 0; r < NN; r++) {
        int v = (int)order_[r];
        int xv = v / GRID, yv = v % GRID;
        int root = 0xFFFF;
        if (lane < nn) {
            int xu = xv + c_dxs[lane], yu = yv + c_dys[lane];
            if ((unsigned)xu < (unsigned)GRID && (unsigned)yu < (unsigned)GRID) {
                int u = xu * GRID + yu;
                if ((int)pos_[u] < r) {  // neighbor already added
                    int xx = u;
                    for (;;) {  // find with path halving (concurrent-safe)
                        int p = par[xx];
                        if (p == xx) { root = xx; break; }
                        int gp = par[p];
                        if (gp != p) par[xx] = (unsigned short)gp;
                        xx = gp;
                    }
                }
            }
        }
        if (lane < 8) sroots[lane] = (unsigned short)root;
        __syncwarp();
        if (lane == 0) {
            int rv = v;  // freshly added vertex is its own root
            for (int l = 0; l < nn; l++) {
                int ru = (int)sroots[l];
                if (ru == 0xFFFF) continue;
                while ((int)par[ru] != ru) ru = (int)par[ru];  // refresh (short)
                if (ru == rv) continue;
                int bu = (int)birthp_[ru], bv = (int)birthp_[rv];
                int lbp;
                if (bu <= bv) { lbp = bv; par[rv] = (unsigned short)ru; rv = ru; }
                else          { lbp = bu; par[ru] = (unsigned short)rv; }
                int lbv = (int)order_[lbp];
                float Bv, Dv;
                if (dir == 0) { Bv = vals[lbv]; Dv = vals[v]; }
                else          { Bv = vals[v];   Dv = vals[lbv]; }  // (bi,di)=(d1,b1) swap
                pB[k] = Bv;
                pD[k] = Dv;
                k++;
            }
        }
        __syncwarp();
    }
}

// ---------------------------------------------------------------------------
// Kernel D: landscape top-K features + both dense layers. Block per image.
// ---------------------------------------------------------------------------
__global__ void landscape_mlp_kernel(const float* __restrict__ wg1, const float* __restrict__ bg1,
                                     const float* __restrict__ wg2, const float* __restrict__ bg2,
                                     const float* __restrict__ wfc, const float* __restrict__ bfc,
                                     float* __restrict__ out) {
    int m = blockIdx.x;
    __shared__ float feats[320];  // [0..127]=g1 (2*2*32), [128..319]=g2 (2*3*32)
    __shared__ float sx[64];
    int tid = threadIdx.x;
    int lane = tid & 31, warp = tid >> 5;

    // 128 jobs: (g, dir, ti). Each warp: register top-3 then merge-pop across lanes.
    for (int q = warp; q < 128; q += 8) {
        int g = q >> 6;
        int rem = q & 63;
        int dir = rem >> 5;
        int ti = rem & 31;
        int K = g ? 3 : 2;
        float t = g ? (1.0f + 7.0f * (float)ti / 31.0f) : (7.0f * (float)ti / 31.0f);
        int task = ((m * 2 + g) * 2 + dir);
        const float* pb = g_pB + task * NN;
        const float* pd = g_pD + task * NN;
        float a0 = -1.f, a1 = -1.f, a2 = -1.f;
        for (int j = lane; j < NN; j += 32) {
            float tent = fmaxf(fminf(t - pb[j], pd[j] - t), 0.f);
            if (tent > a2) {
                if (tent > a0)      { a2 = a1; a1 = a0; a0 = tent; }
                else if (tent > a1) { a2 = a1; a1 = tent; }
                else                { a2 = tent; }
            }
        }
        for (int kk = 0; kk < K; kk++) {
            float w = a0;
#pragma unroll
            for (int off = 16; off; off >>= 1) w = fmaxf(w, __shfl_xor_sync(0xFFFFFFFFu, w, off));
            unsigned bal = __ballot_sync(0xFFFFFFFFu, a0 == w);
            int src = __ffs(bal) - 1;
            if (lane == src) { a0 = a1; a1 = a2; a2 = -1.f; }
            if (lane == 0) feats[(g ? 128 : 0) + (dir * K + kk) * 32 + ti] = w;
        }
    }
    __syncthreads();

    if (tid < 32) {
        float a = bg1[tid];
#pragma unroll 4
        for (int c = 0; c < 128; c++) a += feats[c] * wg1[tid * 128 + c];
        sx[tid] = fmaxf(a, 0.f);
    } else if (tid < 64) {
        int o = tid - 32;
        float a = bg2[o];
#pragma unroll 4
        for (int c = 0; c < 192; c++) a += feats[128 + c] * wg2[o * 192 + c];
        sx[tid] = fmaxf(a, 0.f);
    }
    __syncthreads();
    if (tid < 10) {
        float a = bfc[tid];
#pragma unroll
        for (int c = 0; c < 64; c++) a += sx[c] * wfc[tid * 64 + c];
        out[m * 10 + tid] = a;
    }
}

// ---------------------------------------------------------------------------
extern "C" void kernel_launch(void* const* d_in, const int* in_sizes, int n_in,
                              void* d_out, int out_size) {
    const float* x   = (const float*)d_in[0];
    const float* wg1 = (const float*)d_in[1];
    const float* bg1 = (const float*)d_in[2];
    const float* wg2 = (const float*)d_in[3];
    const float* bg2 = (const float*)d_in[4];
    const float* wfc = (const float*)d_in[5];
    const float* bfc = (const float*)d_in[6];
    float* out = (float*)d_out;
    int B = in_sizes[0] / NN;
    if (B > MAXB) B = MAXB;

    build_sort_table_kernel<<<NN, 256>>>();
    dtm_kernel<<<B, 256>>>(x);
    pairs_kernel<<<B * 4, 256>>>();
    landscape_mlp_kernel<<<B, 256>>>(wg1, bg1, wg2, bg2, wfc, bfc, out);
}

// round 2
// speedup vs baseline: 1.0270x; 1.0270x over previous
#include <cuda_runtime.h>

#define NN 784
#define GRID 28
#define MAXB 64
#define MAXD2 1459   // d2 in [0, 27^2+27^2=1458]

// Scratch (device globals — no allocations allowed)
__device__ unsigned short g_sort_idx[NN * NN];   // [i][rank] -> neighbor index
__device__ float g_fvals[2 * MAXB * NN];         // [g][m][i] dtm values
__device__ float g_feats[MAXB * 320];            // landscape features per image

__constant__ int c_dxs[8] = {-1, 1, 0, 0, -1, -1, 1, 1};
__constant__ int c_dys[8] = {0, 0, -1, 1, -1, 1, -1, 1};

// ---------------------------------------------------------------------------
// Kernel A: stable argsort of squared grid distances per point (counting sort)
// ---------------------------------------------------------------------------
__global__ void build_sort_table_kernel() {
    int i = blockIdx.x;
    int xi = i / GRID, yi = i % GRID;
    __shared__ unsigned int hist[MAXD2];
    __shared__ unsigned short d2a[NN];
    __shared__ unsigned int wsum[8];
    int tid = threadIdx.x;
    int lane = tid & 31, warp = tid >> 5;

    for (int t = tid; t < MAXD2; t += 256) hist[t] = 0u;
    __syncthreads();
    for (int j = tid; j < NN; j += 256) {
        int dx = j / GRID - xi, dy = j % GRID - yi;
        int d2 = dx * dx + dy * dy;
        d2a[j] = (unsigned short)d2;
        atomicAdd(&hist[d2], 1u);
    }
    __syncthreads();

    // exclusive scan of hist[0..1458] (6 entries per thread, 256 threads)
    unsigned int lv[6];
    unsigned int s = 0u;
    int base = tid * 6;
#pragma unroll
    for (int c = 0; c < 6; c++) {
        unsigned int v = (base + c < MAXD2) ? hist[base + c] : 0u;
        lv[c] = s;
        s += v;
    }
    unsigned int inc = s;
#pragma unroll
    for (int off = 1; off < 32; off <<= 1) {
        unsigned int t = __shfl_up_sync(0xFFFFFFFFu, inc, off);
        if (lane >= off) inc += t;
    }
    if (lane == 31) wsum[warp] = inc;
    __syncthreads();
    if (tid == 0) {
        unsigned int a = 0u;
        for (int w = 0; w < 8; w++) { unsigned int t = wsum[w]; wsum[w] = a; a += t; }
    }
    __syncthreads();
    unsigned int off0 = wsum[warp] + (inc - s);
    __syncthreads();  // all reads of hist done before overwrite
#pragma unroll
    for (int c = 0; c < 6; c++)
        if (base + c < MAXD2) hist[base + c] = off0 + lv[c];
    __syncthreads();

    // Stable scatter: warps serialized in ascending-j order
    for (int gq = 0; gq < 25; gq++) {
        if (warp == (gq & 7)) {
            int j = gq * 32 + lane;
            bool valid = (j < NN);
            unsigned int key = valid ? (unsigned int)d2a[j] : 0xFFFFu;
            unsigned int mk = __match_any_sync(0xFFFFFFFFu, key);
            int leader = __ffs(mk) - 1;
            int pre = __popc(mk & ((1u << lane) - 1u));
            unsigned int b0 = 0u;
            if (lane == leader && valid) b0 = atomicAdd(&hist[key], (unsigned int)__popc(mk));
            b0 = __shfl_sync(0xFFFFFFFFu, b0, leader);
            if (valid) g_sort_idx[i * NN + b0 + pre] = (unsigned short)j;
        }
        __syncthreads();
    }
}

// ---------------------------------------------------------------------------
// Kernel B: DTM for both m0 values in a single pass. Grid (B, 4): 4 blocks/img.
// ---------------------------------------------------------------------------
__global__ void dtm_kernel(const float* __restrict__ x) {
    int m = blockIdx.x;
    __shared__ float img[NN];
    __shared__ float red[8];
    int tid = threadIdx.x;
    int lane = tid & 31, warp = tid >> 5;

    float ps = 0.f;
    for (int j = tid; j < NN; j += 256) {
        float v = x[m * NN + j];
        img[j] = v;
        ps += v;
    }
#pragma unroll
    for (int off = 16; off; off >>= 1) ps += __shfl_xor_sync(0xFFFFFFFFu, ps, off);
    if (lane == 0) red[warp] = ps;
    __syncthreads();
    float S = 0.f;
#pragma unroll
    for (int w = 0; w < 8; w++) S += red[w];
    float bound1 = 0.05f * S;
    float bound2 = 0.2f * S;

    int wglob = blockIdx.y * 8 + warp;   // 32 warps per image
    for (int i = wglob; i < NN; i += 32) {
        int xi = i / GRID, yi = i % GRID;
        float acc1 = 0.f, acc2 = 0.f, running = 0.f;
        for (int c = 0; c < NN; c += 32) {
            int j = c + lane;
            float w = 0.f, fd2 = 0.f;
            if (j < NN) {
                int idx = (int)g_sort_idx[i * NN + j];
                w = img[idx];
                int dx = idx / GRID - xi, dy = idx % GRID - yi;
                fd2 = (float)(dx * dx + dy * dy);
            }
            float cs = w;
#pragma unroll
            for (int off = 1; off < 32; off <<= 1) {
                float t = __shfl_up_sync(0xFFFFFFFFu, cs, off);
                if (lane >= off) cs += t;
            }
            float cumBefore = running + cs - w;
            float e1 = fminf(fmaxf(bound1 - cumBefore, 0.f), w);
            float e2 = fminf(fmaxf(bound2 - cumBefore, 0.f), w);
            acc1 += e1 * fd2;
            acc2 += e2 * fd2;
            running += __shfl_sync(0xFFFFFFFFu, cs, 31);
            if (running >= bound2) break;  // all further eff are exactly 0
        }
#pragma unroll
        for (int off = 16; off; off >>= 1) {
            acc1 += __shfl_xor_sync(0xFFFFFFFFu, acc1, off);
            acc2 += __shfl_xor_sync(0xFFFFFFFFu, acc2, off);
        }
        if (lane == 0) {
            g_fvals[(0 * MAXB + m) * NN + i] = sqrtf(acc1 / bound1);
            g_fvals[(1 * MAXB + m) * NN + i] = sqrtf(acc2 / bound2);
        }
    }
}

// ---------------------------------------------------------------------------
// Kernel C: per-task stable sort (bitonic) + register-critical-path union-find
// + fused landscape top-K. block = m*2+g; DIR is a template param.
// ---------------------------------------------------------------------------
template <int DIR>
__global__ void pairs_kernel(int B) {
    int blk = blockIdx.x;
    int g = blk & 1;
    int m = blk >> 1;

    __shared__ float vals[NN];
    __shared__ unsigned long long keys[1024];
    __shared__ unsigned short order_[NN], pos_[NN], parent_[NN], birthp_[NN];
    __shared__ float spB[NN], spD[NN];
    int tid = threadIdx.x;
    int lane = tid & 31, warp = tid >> 5;
    const int NNB = DIR ? 8 : 4;

    for (int j = tid; j < NN; j += 256) {
        float v = g_fvals[(g * MAXB + m) * NN + j];
        vals[j] = v;
        float kf = DIR ? -v : v;  // dir1: superlevel via -x
        unsigned int u = __float_as_uint(kf);
        u = (u & 0x80000000u) ? ~u : (u | 0x80000000u);  // sortable transform
        keys[j] = ((unsigned long long)u << 32) | (unsigned int)j;  // stable ties by j
        spB[j] = 0.f;
        spD[j] = 0.f;
    }
    for (int j = NN + tid; j < 1024; j += 256) keys[j] = ~0ULL;
    __syncthreads();

    // bitonic sort of 1024 keys
    for (int k = 2; k <= 1024; k <<= 1) {
        for (int jj = k >> 1; jj > 0; jj >>= 1) {
            for (int i = tid; i < 1024; i += 256) {
                int ixj = i ^ jj;
                if (ixj > i) {
                    unsigned long long a = keys[i], b = keys[ixj];
                    bool up = ((i & k) == 0);
                    if ((a > b) == up) { keys[i] = b; keys[ixj] = a; }
                }
            }
            __syncthreads();
        }
    }

    for (int r = tid; r < NN; r += 256) {
        int j = (int)(unsigned int)keys[r];
        order_[r] = (unsigned short)j;
        pos_[j] = (unsigned short)r;
        parent_[j] = (unsigned short)j;
        birthp_[j] = (unsigned short)r;  // birth pos of singleton = own pos (never mutated)
    }
    __syncthreads();

    // ---- union-find: warp 0, merge logic fully in registers ----
    if (tid < 32) {
        volatile unsigned short* par = parent_;
        int k = 0;
        for (int r = 0; r < NN; r++) {
            int v = (int)order_[r];
            int xv = v / GRID, yv = v % GRID;
            unsigned packed = 0xFFFFFFFFu;
            if (lane < NNB) {
                int xu = xv + c_dxs[lane], yu = yv + c_dys[lane];
                if ((unsigned)xu < (unsigned)GRID && (unsigned)yu < (unsigned)GRID) {
                    int u = xu * GRID + yu;
                    if ((int)pos_[u] < r) {  // neighbor already added
                        int xx = u;
                        for (;;) {  // find with path halving (concurrent-safe)
                            int p = par[xx];
                            if (p == xx) break;
                            int gp = par[p];
                            if (gp != p) par[xx] = (unsigned short)gp;
                            xx = gp;
                        }
                        packed = ((unsigned)xx << 16) | (unsigned)birthp_[xx];
                    }
                }
            }
            unsigned pk[8];
#pragma unroll
            for (int l = 0; l < 8; l++)
                pk[l] = (l < NNB) ? __shfl_sync(0xFFFFFFFFu, packed, l) : 0xFFFFFFFFu;

            // redundant merge on all lanes (registers only); lane 0 stores
            int rv = v, bv = r;
            int seen[7];
            int nseen = 0;
#pragma unroll
            for (int l = 0; l < 8; l++) {
                if (l >= NNB) break;
                unsigned p = pk[l];
                if (p == 0xFFFFFFFFu) continue;
                int ru = (int)(p >> 16);
                int bu = (int)(p & 0xFFFFu);
                bool dup = (ru == rv);
#pragma unroll
                for (int s = 0; s < 7; s++) dup = dup || ((s < nseen) && (seen[s] == ru));
                if (dup) continue;
                int loser, lbp;
                if (bu <= bv) { loser = rv; lbp = bv; rv = ru; bv = bu; }
                else          { loser = ru; lbp = bu; }
                if (lane == 0) par[loser] = (unsigned short)rv;
#pragma unroll
                for (int s = 0; s < 7; s++) if (s == nseen) seen[s] = loser;
                nseen++;
                int lbv = (int)order_[lbp];
                float Bv, Dv;
                if (DIR == 0) { Bv = vals[lbv]; Dv = vals[v]; }
                else          { Bv = vals[v];   Dv = vals[lbv]; }  // (bi,di)=(d1,b1) swap
                if (lane == 0) { spB[k] = Bv; spD[k] = Dv; }
                k++;
            }
            __syncwarp();
        }
    }
    __syncthreads();

    // ---- fused landscape top-K: 32 t-values, warp per t ----
    int K = g ? 3 : 2;
    float start = g ? 1.0f : 0.0f;
    int fbase = m * 320 + (g ? 128 : 0);
    for (int ti = warp; ti < 32; ti += 8) {
        float t = start + 7.0f * (float)ti / 31.0f;
        float a0 = -1.f, a1 = -1.f, a2 = -1.f;
        for (int j = lane; j < NN; j += 32) {
            float tent = fmaxf(fminf(t - spB[j], spD[j] - t), 0.f);
            if (tent > a2) {
                if (tent > a0)      { a2 = a1; a1 = a0; a0 = tent; }
                else if (tent > a1) { a2 = a1; a1 = tent; }
                else                { a2 = tent; }
            }
        }
        for (int kk = 0; kk < K; kk++) {
            float w = a0;
#pragma unroll
            for (int off = 16; off; off >>= 1) w = fmaxf(w, __shfl_xor_sync(0xFFFFFFFFu, w, off));
            unsigned bal = __ballot_sync(0xFFFFFFFFu, a0 == w);
            int src = __ffs(bal) - 1;
            if (lane == src) { a0 = a1; a1 = a2; a2 = -1.f; }
            if (lane == 0) g_feats[fbase + (DIR * K + kk) * 32 + ti] = w;
        }
    }
}

// ---------------------------------------------------------------------------
// Kernel D: tiny MLP. Block per image, 64 threads.
// ---------------------------------------------------------------------------
__global__ void mlp_kernel(const float* __restrict__ wg1, const float* __restrict__ bg1,
                           const float* __restrict__ wg2, const float* __restrict__ bg2,
                           const float* __restrict__ wfc, const float* __restrict__ bfc,
                           float* __restrict__ out) {
    int m = blockIdx.x;
    __shared__ float sx[64];
    int tid = threadIdx.x;
    const float* feats = g_feats + m * 320;

    if (tid < 32) {
        float a = bg1[tid];
#pragma unroll 4
        for (int c = 0; c < 128; c++) a += feats[c] * wg1[tid * 128 + c];
        sx[tid] = fmaxf(a, 0.f);
    } else {
        int o = tid - 32;
        float a = bg2[o];
#pragma unroll 4
        for (int c = 0; c < 192; c++) a += feats[128 + c] * wg2[o * 192 + c];
        sx[tid] = fmaxf(a, 0.f);
    }
    __syncthreads();
    if (tid < 10) {
        float a = bfc[tid];
#pragma unroll
        for (int c = 0; c < 64; c++) a += sx[c] * wfc[tid * 64 + c];
        out[m * 10 + tid] = a;
    }
}

// ---------------------------------------------------------------------------
extern "C" void kernel_launch(void* const* d_in, const int* in_sizes, int n_in,
                              void* d_out, int out_size) {
    const float* x   = (const float*)d_in[0];
    const float* wg1 = (const float*)d_in[1];
    const float* bg1 = (const float*)d_in[2];
    const float* wg2 = (const float*)d_in[3];
    const float* bg2 = (const float*)d_in[4];
    const float* wfc = (const float*)d_in[5];
    const float* bfc = (const float*)d_in[6];
    float* out = (float*)d_out;
    int B = in_sizes[0] / NN;
    if (B > MAXB) B = MAXB;

    build_sort_table_kernel<<<NN, 256>>>();
    dtm_kernel<<<dim3(B, 4), 256>>>(x);
    pairs_kernel<0><<<B * 2, 256>>>(B);
    pairs_kernel<1><<<B * 2, 256>>>(B);
    mlp_kernel<<<B, 64>>>(wg1, bg1, wg2, bg2, wfc, bfc, out);
}

// round 3
// speedup vs baseline: 2.0927x; 2.0377x over previous
#include <cuda_runtime.h>

#define NN 784
#define GRID 28
#define MAXB 64
#define MAXD2 1459   // d2 in [0, 27^2+27^2=1458]

// Scratch (device globals — no allocations allowed)
__device__ unsigned short g_sort_idx[NN * NN];   // [i][rank] -> neighbor index
__device__ float g_fvals[2 * MAXB * NN];         // [g][m][i] dtm values
__device__ float g_feats[MAXB * 320];            // landscape features per image

__constant__ int c_dxs[8] = {-1, 1, 0, 0, -1, -1, 1, 1};
__constant__ int c_dys[8] = {0, 0, -1, 1, -1, 1, -1, 1};
__constant__ int c_off[8] = {-28, 28, -1, 1, -29, -27, 27, 29};

// ---------------------------------------------------------------------------
// Kernel A: stable argsort of squared grid distances per point (counting sort)
// ---------------------------------------------------------------------------
__global__ void build_sort_table_kernel() {
    int i = blockIdx.x;
    int xi = i / GRID, yi = i % GRID;
    __shared__ unsigned int hist[MAXD2];
    __shared__ unsigned short d2a[NN];
    __shared__ unsigned int wsum[8];
    int tid = threadIdx.x;
    int lane = tid & 31, warp = tid >> 5;

    for (int t = tid; t < MAXD2; t += 256) hist[t] = 0u;
    __syncthreads();
    for (int j = tid; j < NN; j += 256) {
        int dx = j / GRID - xi, dy = j % GRID - yi;
        int d2 = dx * dx + dy * dy;
        d2a[j] = (unsigned short)d2;
        atomicAdd(&hist[d2], 1u);
    }
    __syncthreads();

    // exclusive scan of hist[0..1458] (6 entries per thread, 256 threads)
    unsigned int lv[6];
    unsigned int s = 0u;
    int base = tid * 6;
#pragma unroll
    for (int c = 0; c < 6; c++) {
        unsigned int v = (base + c < MAXD2) ? hist[base + c] : 0u;
        lv[c] = s;
        s += v;
    }
    unsigned int inc = s;
#pragma unroll
    for (int off = 1; off < 32; off <<= 1) {
        unsigned int t = __shfl_up_sync(0xFFFFFFFFu, inc, off);
        if (lane >= off) inc += t;
    }
    if (lane == 31) wsum[warp] = inc;
    __syncthreads();
    if (tid == 0) {
        unsigned int a = 0u;
        for (int w = 0; w < 8; w++) { unsigned int t = wsum[w]; wsum[w] = a; a += t; }
    }
    __syncthreads();
    unsigned int off0 = wsum[warp] + (inc - s);
    __syncthreads();  // all reads of hist done before overwrite
#pragma unroll
    for (int c = 0; c < 6; c++)
        if (base + c < MAXD2) hist[base + c] = off0 + lv[c];
    __syncthreads();

    // Stable scatter: warps serialized in ascending-j order
    for (int gq = 0; gq < 25; gq++) {
        if (warp == (gq & 7)) {
            int j = gq * 32 + lane;
            bool valid = (j < NN);
            unsigned int key = valid ? (unsigned int)d2a[j] : 0xFFFFu;
            unsigned int mk = __match_any_sync(0xFFFFFFFFu, key);
            int leader = __ffs(mk) - 1;
            int pre = __popc(mk & ((1u << lane) - 1u));
            unsigned int b0 = 0u;
            if (lane == leader && valid) b0 = atomicAdd(&hist[key], (unsigned int)__popc(mk));
            b0 = __shfl_sync(0xFFFFFFFFu, b0, leader);
            if (valid) g_sort_idx[i * NN + b0 + pre] = (unsigned short)j;
        }
        __syncthreads();
    }
}

// ---------------------------------------------------------------------------
// Kernel B: DTM for both m0 values in a single pass. Grid (B, 4): 4 blocks/img.
// ---------------------------------------------------------------------------
__global__ void dtm_kernel(const float* __restrict__ x) {
    int m = blockIdx.x;
    __shared__ float img[NN];
    __shared__ float red[8];
    int tid = threadIdx.x;
    int lane = tid & 31, warp = tid >> 5;

    float ps = 0.f;
    for (int j = tid; j < NN; j += 256) {
        float v = x[m * NN + j];
        img[j] = v;
        ps += v;
    }
#pragma unroll
    for (int off = 16; off; off >>= 1) ps += __shfl_xor_sync(0xFFFFFFFFu, ps, off);
    if (lane == 0) red[warp] = ps;
    __syncthreads();
    float S = 0.f;
#pragma unroll
    for (int w = 0; w < 8; w++) S += red[w];
    float bound1 = 0.05f * S;
    float bound2 = 0.2f * S;

    int wglob = blockIdx.y * 8 + warp;   // 32 warps per image
    for (int i = wglob; i < NN; i += 32) {
        int xi = i / GRID, yi = i % GRID;
        float acc1 = 0.f, acc2 = 0.f, running = 0.f;
        for (int c = 0; c < NN; c += 32) {
            int j = c + lane;
            float w = 0.f, fd2 = 0.f;
            if (j < NN) {
                int idx = (int)g_sort_idx[i * NN + j];
                w = img[idx];
                int dx = idx / GRID - xi, dy = idx % GRID - yi;
                fd2 = (float)(dx * dx + dy * dy);
            }
            float cs = w;
#pragma unroll
            for (int off = 1; off < 32; off <<= 1) {
                float t = __shfl_up_sync(0xFFFFFFFFu, cs, off);
                if (lane >= off) cs += t;
            }
            float cumBefore = running + cs - w;
            float e1 = fminf(fmaxf(bound1 - cumBefore, 0.f), w);
            float e2 = fminf(fmaxf(bound2 - cumBefore, 0.f), w);
            acc1 += e1 * fd2;
            acc2 += e2 * fd2;
            running += __shfl_sync(0xFFFFFFFFu, cs, 31);
            if (running >= bound2) break;  // all further eff are exactly 0
        }
#pragma unroll
        for (int off = 16; off; off >>= 1) {
            acc1 += __shfl_xor_sync(0xFFFFFFFFu, acc1, off);
            acc2 += __shfl_xor_sync(0xFFFFFFFFu, acc2, off);
        }
        if (lane == 0) {
            g_fvals[(0 * MAXB + m) * NN + i] = sqrtf(acc1 / bound1);
            g_fvals[(1 * MAXB + m) * NN + i] = sqrtf(acc2 / bound2);
        }
    }
}

// ---------------------------------------------------------------------------
// Kernel C: per-task stable sort (bitonic) + match-dedupe union-find
// + fused landscape top-K. One launch: task = blockIdx.x = ((m*2+g)*2+dir).
// ---------------------------------------------------------------------------
struct SmemC {
    unsigned long long keys[1024];
    float vals[NN];
    unsigned order32[NN + 1];      // (yj<<24)|(xj<<16)|j per rank
    unsigned par32[NN];            // root: (birth_pos<<16)|root ; non-root: low16=parent
    unsigned short pos_[NN];
    float spB[NN], spD[NN];
};

template <int DIR>
__device__ __forceinline__ void pairs_body(SmemC* s, int g, int m) {
    int tid = threadIdx.x;
    int lane = tid & 31, warp = tid >> 5;
    const int NNB = DIR ? 8 : 4;

    for (int j = tid; j < NN; j += 256) {
        float v = g_fvals[(g * MAXB + m) * NN + j];
        s->vals[j] = v;
        float kf = DIR ? -v : v;  // dir1: superlevel via -x
        unsigned int u = __float_as_uint(kf);
        u = (u & 0x80000000u) ? ~u : (u | 0x80000000u);  // sortable transform
        s->keys[j] = ((unsigned long long)u << 32) | (unsigned int)j;  // stable ties by j
        s->spB[j] = 0.f;
        s->spD[j] = 0.f;
    }
    for (int j = NN + tid; j < 1024; j += 256) s->keys[j] = ~0ULL;
    __syncthreads();

    // bitonic sort of 1024 keys
    for (int k = 2; k <= 1024; k <<= 1) {
        for (int jj = k >> 1; jj > 0; jj >>= 1) {
            for (int i = tid; i < 1024; i += 256) {
                int ixj = i ^ jj;
                if (ixj > i) {
                    unsigned long long a = s->keys[i], b = s->keys[ixj];
                    bool up = ((i & k) == 0);
                    if ((a > b) == up) { s->keys[i] = b; s->keys[ixj] = a; }
                }
            }
            __syncthreads();
        }
    }

    for (int r = tid; r < NN; r += 256) {
        int j = (int)(unsigned int)s->keys[r];
        int xj = j / GRID, yj = j % GRID;
        s->order32[r] = (unsigned)j | ((unsigned)xj << 16) | ((unsigned)yj << 24);
        s->pos_[j] = (unsigned short)r;
        s->par32[j] = ((unsigned)r << 16) | (unsigned)j;   // root: birth<<16 | self
    }
    if (tid == 0) s->order32[NN] = 0u;
    __syncthreads();

    // ---- union-find: warp 0. packed = (birth_pos<<16)|root; smaller birth wins ----
    if (tid < 32) {
        volatile unsigned* par = s->par32;
        int k = 0;
        unsigned ordv = s->order32[0];
        for (int r = 0; r < NN; r++) {
            unsigned ordn = s->order32[r + 1];   // prefetch
            int v = (int)(ordv & 0xFFFFu);
            int xv = (int)((ordv >> 16) & 0xFFu), yv = (int)(ordv >> 24);
            unsigned packed = 0xFFFFFFFFu;
            if (lane < NNB) {
                int xu = xv + c_dxs[lane], yu = yv + c_dys[lane];
                if ((unsigned)xu < (unsigned)GRID && (unsigned)yu < (unsigned)GRID) {
                    int u = v + c_off[lane];
                    if ((int)s->pos_[u] < r) {  // neighbor already added
                        int xx = u;
                        for (;;) {  // find, 2 levels/iter with path halving
                            unsigned p32 = par[xx];
                            int pl = (int)(p32 & 0xFFFFu);
                            if (pl == xx) { packed = p32; break; }
                            unsigned q32 = par[pl];
                            int ql = (int)(q32 & 0xFFFFu);
                            if (ql == pl) { packed = q32; break; }
                            par[xx] = q32;      // halve: xx -> grandparent
                            xx = ql;
                        }
                    }
                }
            }
            bool valid = (packed != 0xFFFFFFFFu);
            unsigned grp = __match_any_sync(0xFFFFFFFFu, packed);
            bool leader = ((grp & ((1u << lane) - 1u)) == 0u);
            unsigned mask = __ballot_sync(0xFFFFFFFFu, valid && leader);
            unsigned pv = ((unsigned)r << 16) | (unsigned)v;
            while (mask) {
                int l = __ffs(mask) - 1;
                mask &= mask - 1;
                unsigned pu = __shfl_sync(0xFFFFFFFFu, packed, l);
                unsigned win = pu < pv ? pu : pv;
                unsigned lose = pu < pv ? pv : pu;
                if (lane == 0) {
                    par[lose & 0xFFFFu] = win;          // low16 = winner root
                    int lbv = (int)(s->order32[lose >> 16] & 0xFFFFu);
                    float Bv, Dv;
                    if (DIR == 0) { Bv = s->vals[lbv]; Dv = s->vals[v]; }
                    else          { Bv = s->vals[v];   Dv = s->vals[lbv]; }
                    s->spB[k] = Bv;
                    s->spD[k] = Dv;
                }
                pv = win;
                k++;
            }
            __syncwarp();
            ordv = ordn;
        }
    }
    __syncthreads();

    // ---- fused landscape top-K: 32 t-values, warp per t ----
    int K = g ? 3 : 2;
    float start = g ? 1.0f : 0.0f;
    int fbase = m * 320 + (g ? 128 : 0);
    for (int ti = warp; ti < 32; ti += 8) {
        float t = start + 7.0f * (float)ti / 31.0f;
        float a0 = -1.f, a1 = -1.f, a2 = -1.f;
        for (int j = lane; j < NN; j += 32) {
            float tent = fmaxf(fminf(t - s->spB[j], s->spD[j] - t), 0.f);
            if (tent > a2) {
                if (tent > a0)      { a2 = a1; a1 = a0; a0 = tent; }
                else if (tent > a1) { a2 = a1; a1 = tent; }
                else                { a2 = tent; }
            }
        }
        for (int kk = 0; kk < K; kk++) {
            float w = a0;
#pragma unroll
            for (int off = 16; off; off >>= 1) w = fmaxf(w, __shfl_xor_sync(0xFFFFFFFFu, w, off));
            unsigned bal = __ballot_sync(0xFFFFFFFFu, a0 == w);
            int src = __ffs(bal) - 1;
            if (lane == src) { a0 = a1; a1 = a2; a2 = -1.f; }
            if (lane == 0) g_feats[fbase + (DIR * K + kk) * 32 + ti] = w;
        }
    }
}

__global__ void pairs_kernel() {
    __shared__ SmemC smc;
    int task = blockIdx.x;
    int dir = task & 1;
    int g = (task >> 1) & 1;
    int m = task >> 2;
    if (dir == 0) pairs_body<0>(&smc, g, m);
    else          pairs_body<1>(&smc, g, m);
}

// ---------------------------------------------------------------------------
// Kernel D: tiny MLP. Block per image, 64 threads.
// ---------------------------------------------------------------------------
__global__ void mlp_kernel(const float* __restrict__ wg1, const float* __restrict__ bg1,
                           const float* __restrict__ wg2, const float* __restrict__ bg2,
                           const float* __restrict__ wfc, const float* __restrict__ bfc,
                           float* __restrict__ out) {
    int m = blockIdx.x;
    __shared__ float sx[64];
    int tid = threadIdx.x;
    const float* feats = g_feats + m * 320;

    if (tid < 32) {
        float a = bg1[tid];
#pragma unroll 4
        for (int c = 0; c < 128; c++) a += feats[c] * wg1[tid * 128 + c];
        sx[tid] = fmaxf(a, 0.f);
    } else {
        int o = tid - 32;
        float a = bg2[o];
#pragma unroll 4
        for (int c = 0; c < 192; c++) a += feats[128 + c] * wg2[o * 192 + c];
        sx[tid] = fmaxf(a, 0.f);
    }
    __syncthreads();
    if (tid < 10) {
        float a = bfc[tid];
#pragma unroll
        for (int c = 0; c < 64; c++) a += sx[c] * wfc[tid * 64 + c];
        out[m * 10 + tid] = a;
    }
}

// ---------------------------------------------------------------------------
extern "C" void kernel_launch(void* const* d_in, const int* in_sizes, int n_in,
                              void* d_out, int out_size) {
    const float* x   = (const float*)d_in[0];
    const float* wg1 = (const float*)d_in[1];
    const float* bg1 = (const float*)d_in[2];
    const float* wg2 = (const float*)d_in[3];
    const float* bg2 = (const float*)d_in[4];
    const float* wfc = (const float*)d_in[5];
    const float* bfc = (const float*)d_in[6];
    float* out = (float*)d_out;
    int B = in_sizes[0] / NN;
    if (B > MAXB) B = MAXB;

    build_sort_table_kernel<<<NN, 256>>>();
    dtm_kernel<<<dim3(B, 4), 256>>>(x);
    pairs_kernel<<<B * 4, 256>>>();
    mlp_kernel<<<B, 64>>>(wg1, bg1, wg2, bg2, wfc, bfc, out);
}

// round 4
// speedup vs baseline: 3.2974x; 1.5757x over previous
#include <cuda_runtime.h>

#define NN 784
#define GRID 28
#define MAXB 64
#define MAXD2 1459   // d2 in [0, 27^2+27^2=1458]

// Scratch (device globals — no allocations allowed)
__device__ unsigned short g_sort_idx[NN * NN];   // [i][rank] -> neighbor index
__device__ float g_fvals[2 * MAXB * NN];         // [g][m][i] dtm values
__device__ float g_feats[MAXB * 320];            // landscape features per image

__constant__ int c_dxs[8] = {-1, 1, 0, 0, -1, -1, 1, 1};
__constant__ int c_dys[8] = {0, 0, -1, 1, -1, 1, -1, 1};
__constant__ int c_off[8] = {-28, 28, -1, 1, -29, -27, 27, 29};

// ---------------------------------------------------------------------------
// Kernel A: stable argsort of squared grid distances per point (counting sort)
// ---------------------------------------------------------------------------
__global__ void build_sort_table_kernel() {
    int i = blockIdx.x;
    int xi = i / GRID, yi = i % GRID;
    __shared__ unsigned int hist[MAXD2];
    __shared__ unsigned short d2a[NN];
    __shared__ unsigned int wsum[8];
    int tid = threadIdx.x;
    int lane = tid & 31, warp = tid >> 5;

    for (int t = tid; t < MAXD2; t += 256) hist[t] = 0u;
    __syncthreads();
    for (int j = tid; j < NN; j += 256) {
        int dx = j / GRID - xi, dy = j % GRID - yi;
        int d2 = dx * dx + dy * dy;
        d2a[j] = (unsigned short)d2;
        atomicAdd(&hist[d2], 1u);
    }
    __syncthreads();

    // exclusive scan of hist[0..1458] (6 entries per thread, 256 threads)
    unsigned int lv[6];
    unsigned int s = 0u;
    int base = tid * 6;
#pragma unroll
    for (int c = 0; c < 6; c++) {
        unsigned int v = (base + c < MAXD2) ? hist[base + c] : 0u;
        lv[c] = s;
        s += v;
    }
    unsigned int inc = s;
#pragma unroll
    for (int off = 1; off < 32; off <<= 1) {
        unsigned int t = __shfl_up_sync(0xFFFFFFFFu, inc, off);
        if (lane >= off) inc += t;
    }
    if (lane == 31) wsum[warp] = inc;
    __syncthreads();
    if (tid == 0) {
        unsigned int a = 0u;
        for (int w = 0; w < 8; w++) { unsigned int t = wsum[w]; wsum[w] = a; a += t; }
    }
    __syncthreads();
    unsigned int off0 = wsum[warp] + (inc - s);
    __syncthreads();  // all reads of hist done before overwrite
#pragma unroll
    for (int c = 0; c < 6; c++)
        if (base + c < MAXD2) hist[base + c] = off0 + lv[c];
    __syncthreads();

    // Stable scatter: warps serialized in ascending-j order
    for (int gq = 0; gq < 25; gq++) {
        if (warp == (gq & 7)) {
            int j = gq * 32 + lane;
            bool valid = (j < NN);
            unsigned int key = valid ? (unsigned int)d2a[j] : 0xFFFFu;
            unsigned int mk = __match_any_sync(0xFFFFFFFFu, key);
            int leader = __ffs(mk) - 1;
            int pre = __popc(mk & ((1u << lane) - 1u));
            unsigned int b0 = 0u;
            if (lane == leader && valid) b0 = atomicAdd(&hist[key], (unsigned int)__popc(mk));
            b0 = __shfl_sync(0xFFFFFFFFu, b0, leader);
            if (valid) g_sort_idx[i * NN + b0 + pre] = (unsigned short)j;
        }
        __syncthreads();
    }
}

// ---------------------------------------------------------------------------
// Kernel B: DTM for both m0 values in a single pass. Grid (B, 4): 4 blocks/img.
// ---------------------------------------------------------------------------
__global__ void dtm_kernel(const float* __restrict__ x) {
    int m = blockIdx.x;
    __shared__ float img[NN];
    __shared__ float red[8];
    int tid = threadIdx.x;
    int lane = tid & 31, warp = tid >> 5;

    float ps = 0.f;
    for (int j = tid; j < NN; j += 256) {
        float v = x[m * NN + j];
        img[j] = v;
        ps += v;
    }
#pragma unroll
    for (int off = 16; off; off >>= 1) ps += __shfl_xor_sync(0xFFFFFFFFu, ps, off);
    if (lane == 0) red[warp] = ps;
    __syncthreads();
    float S = 0.f;
#pragma unroll
    for (int w = 0; w < 8; w++) S += red[w];
    float bound1 = 0.05f * S;
    float bound2 = 0.2f * S;

    int wglob = blockIdx.y * 8 + warp;   // 32 warps per image
    for (int i = wglob; i < NN; i += 32) {
        int xi = i / GRID, yi = i % GRID;
        float acc1 = 0.f, acc2 = 0.f, running = 0.f;
        for (int c = 0; c < NN; c += 32) {
            int j = c + lane;
            float w = 0.f, fd2 = 0.f;
            if (j < NN) {
                int idx = (int)g_sort_idx[i * NN + j];
                w = img[idx];
                int dx = idx / GRID - xi, dy = idx % GRID - yi;
                fd2 = (float)(dx * dx + dy * dy);
            }
            float cs = w;
#pragma unroll
            for (int off = 1; off < 32; off <<= 1) {
                float t = __shfl_up_sync(0xFFFFFFFFu, cs, off);
                if (lane >= off) cs += t;
            }
            float cumBefore = running + cs - w;
            float e1 = fminf(fmaxf(bound1 - cumBefore, 0.f), w);
            float e2 = fminf(fmaxf(bound2 - cumBefore, 0.f), w);
            acc1 += e1 * fd2;
            acc2 += e2 * fd2;
            running += __shfl_sync(0xFFFFFFFFu, cs, 31);
            if (running >= bound2) break;  // all further eff are exactly 0
        }
#pragma unroll
        for (int off = 16; off; off >>= 1) {
            acc1 += __shfl_xor_sync(0xFFFFFFFFu, acc1, off);
            acc2 += __shfl_xor_sync(0xFFFFFFFFu, acc2, off);
        }
        if (lane == 0) {
            g_fvals[(0 * MAXB + m) * NN + i] = sqrtf(acc1 / bound1);
            g_fvals[(1 * MAXB + m) * NN + i] = sqrtf(acc2 / bound2);
        }
    }
}

// ---------------------------------------------------------------------------
// Kernel C: per-task stable sort (bitonic) + flat parallel-merge union-find
// + fused landscape top-K. One launch: task = blockIdx.x = ((m*2+g)*2+dir).
// ---------------------------------------------------------------------------
struct SmemC {
    unsigned long long keys[1024];
    float vals[NN];
    unsigned order32[NN + 1];        // (yj<<24)|(xj<<16)|j per rank
    unsigned par32[NN];              // root: (birth_pos<<16)|root ; else low16=parent
    unsigned short pos_[NN];
    unsigned char nbm[NN];           // per-rank eligible-neighbor bitmask
    float spB[NN], spD[NN];
};

template <int DIR>
__device__ __forceinline__ void pairs_body(SmemC* s, int g, int m) {
    int tid = threadIdx.x;
    int lane = tid & 31, warp = tid >> 5;
    const unsigned EMASK = DIR ? 0xFFu : 0x0Fu;

    for (int j = tid; j < NN; j += 256) {
        float v = g_fvals[(g * MAXB + m) * NN + j];
        s->vals[j] = v;
        float kf = DIR ? -v : v;  // dir1: superlevel via -x
        unsigned int u = __float_as_uint(kf);
        u = (u & 0x80000000u) ? ~u : (u | 0x80000000u);  // sortable transform
        s->keys[j] = ((unsigned long long)u << 32) | (unsigned int)j;  // stable ties by j
        s->spB[j] = 0.f;
        s->spD[j] = 0.f;
    }
    for (int j = NN + tid; j < 1024; j += 256) s->keys[j] = ~0ULL;
    __syncthreads();

    // bitonic sort of 1024 keys
    for (int k = 2; k <= 1024; k <<= 1) {
        for (int jj = k >> 1; jj > 0; jj >>= 1) {
            for (int i = tid; i < 1024; i += 256) {
                int ixj = i ^ jj;
                if (ixj > i) {
                    unsigned long long a = s->keys[i], b = s->keys[ixj];
                    bool up = ((i & k) == 0);
                    if ((a > b) == up) { s->keys[i] = b; s->keys[ixj] = a; }
                }
            }
            __syncthreads();
        }
    }

    for (int r = tid; r < NN; r += 256) {
        int j = (int)(unsigned int)s->keys[r];
        int xj = j / GRID, yj = j % GRID;
        s->order32[r] = (unsigned)j | ((unsigned)xj << 16) | ((unsigned)yj << 24);
        s->pos_[j] = (unsigned short)r;
        s->par32[j] = ((unsigned)r << 16) | (unsigned)j;   // root: birth<<16 | self
    }
    if (tid == 0) s->order32[NN] = 0u;
    __syncthreads();

    // precompute per-rank eligible-neighbor bitmask (pos[u] < r, in bounds)
    for (int r = tid; r < NN; r += 256) {
        unsigned o = s->order32[r];
        int v = (int)(o & 0xFFFFu);
        int xv = (int)((o >> 16) & 0xFFu), yv = (int)(o >> 24);
        unsigned mask = 0u;
#pragma unroll
        for (int l = 0; l < 8; l++) {
            int xu = xv + c_dxs[l], yu = yv + c_dys[l];
            if ((unsigned)xu < (unsigned)GRID && (unsigned)yu < (unsigned)GRID &&
                (int)s->pos_[v + c_off[l]] < r)
                mask |= 1u << l;
        }
        s->nbm[r] = (unsigned char)mask;
    }
    __syncthreads();

    // ---- union-find: warp 0. packed = (birth_pos<<16)|root; min packed wins ----
    if (tid < 32) {
        volatile unsigned* par = s->par32;
        int k = 0;
        unsigned ordv = s->order32[0];
        unsigned em = (unsigned)s->nbm[0] & EMASK;
        unsigned lmlt = (1u << lane) - 1u;
        for (int r = 0; r < NN; r++) {
            unsigned ordn = s->order32[r + 1];            // prefetch
            unsigned emn = (unsigned)s->nbm[(r + 1 == NN) ? 0 : r + 1] & EMASK;
            int v = (int)(ordv & 0xFFFFu);
            unsigned packed = 0xFFFFFFFFu;
            if ((em >> lane) & 1u) {
                int xx = v + c_off[lane];
                for (;;) {  // find, 2 levels/iter with path halving
                    unsigned p32 = par[xx];
                    int pl = (int)(p32 & 0xFFFFu);
                    if (pl == xx) { packed = p32; break; }
                    unsigned q32 = par[pl];
                    int ql = (int)(q32 & 0xFFFFu);
                    if (ql == pl) { packed = q32; break; }
                    par[xx] = q32;      // halve: xx -> grandparent
                    xx = ql;
                }
            }
            unsigned wmin = __reduce_min_sync(0xFFFFFFFFu, packed);
            bool anyv = (wmin != 0xFFFFFFFFu);   // any eligible neighbor found
            unsigned grp = __match_any_sync(0xFFFFFFFFu, packed);
            bool leader = (packed != 0xFFFFFFFFu) && ((grp & lmlt) == 0u);
            bool loser = leader && (packed != wmin);
            unsigned lmask = __ballot_sync(0xFFFFFFFFu, loser);
            if (loser) {
                par[packed & 0xFFFFu] = wmin;           // point loser at final winner
                int rk = k + __popc(lmask & lmlt);
                int lbv = (int)(s->order32[packed >> 16] & 0xFFFFu);
                float Bv, Dv;
                if (DIR == 0) { Bv = s->vals[lbv]; Dv = s->vals[v]; }
                else          { Bv = s->vals[v];   Dv = s->vals[lbv]; }
                s->spB[rk] = Bv;
                s->spD[rk] = Dv;
            }
            if (anyv && lane == 0) par[v] = wmin;  // v's fresh component always loses
            k += __popc(lmask);                    // (v,v) zero-persistence pair skipped
            __syncwarp();
            ordv = ordn;
            em = emn;
        }
    }
    __syncthreads();

    // ---- fused landscape top-K: 32 t-values, warp per t ----
    int K = g ? 3 : 2;
    float start = g ? 1.0f : 0.0f;
    int fbase = m * 320 + (g ? 128 : 0);
    for (int ti = warp; ti < 32; ti += 8) {
        float t = start + 7.0f * (float)ti / 31.0f;
        float a0 = -1.f, a1 = -1.f, a2 = -1.f;
        for (int j = lane; j < NN; j += 32) {
            float tent = fmaxf(fminf(t - s->spB[j], s->spD[j] - t), 0.f);
            if (tent > a2) {
                if (tent > a0)      { a2 = a1; a1 = a0; a0 = tent; }
                else if (tent > a1) { a2 = a1; a1 = tent; }
                else                { a2 = tent; }
            }
        }
        for (int kk = 0; kk < K; kk++) {
            float w = a0;
#pragma unroll
            for (int off = 16; off; off >>= 1) w = fmaxf(w, __shfl_xor_sync(0xFFFFFFFFu, w, off));
            unsigned bal = __ballot_sync(0xFFFFFFFFu, a0 == w);
            int src = __ffs(bal) - 1;
            if (lane == src) { a0 = a1; a1 = a2; a2 = -1.f; }
            if (lane == 0) g_feats[fbase + (DIR * K + kk) * 32 + ti] = w;
        }
    }
}

__global__ void pairs_kernel() {
    __shared__ SmemC smc;
    int task = blockIdx.x;
    int dir = task & 1;
    int g = (task >> 1) & 1;
    int m = task >> 2;
    if (dir == 0) pairs_body<0>(&smc, g, m);
    else          pairs_body<1>(&smc, g, m);
}

// ---------------------------------------------------------------------------
// Kernel D: tiny MLP. Block per image, 512 threads, warp-per-unit dots.
// ---------------------------------------------------------------------------
__global__ void mlp_kernel(const float* __restrict__ wg1, const float* __restrict__ bg1,
                           const float* __restrict__ wg2, const float* __restrict__ bg2,
                           const float* __restrict__ wfc, const float* __restrict__ bfc,
                           float* __restrict__ out) {
    int m = blockIdx.x;
    __shared__ float sx[64];
    int tid = threadIdx.x;
    int lane = tid & 31, w = tid >> 5;   // 16 warps
    const float* feats = g_feats + m * 320;

#pragma unroll
    for (int i = 0; i < 2; i++) {
        int u = w * 2 + i;
        float a = 0.f;
#pragma unroll
        for (int c = lane; c < 128; c += 32) a += feats[c] * wg1[u * 128 + c];
#pragma unroll
        for (int off = 16; off; off >>= 1) a += __shfl_xor_sync(0xFFFFFFFFu, a, off);
        if (lane == 0) sx[u] = fmaxf(a + bg1[u], 0.f);
    }
#pragma unroll
    for (int i = 0; i < 2; i++) {
        int u = w * 2 + i;
        float a = 0.f;
#pragma unroll
        for (int c = lane; c < 192; c += 32) a += feats[128 + c] * wg2[u * 192 + c];
#pragma unroll
        for (int off = 16; off; off >>= 1) a += __shfl_xor_sync(0xFFFFFFFFu, a, off);
        if (lane == 0) sx[32 + u] = fmaxf(a + bg2[u], 0.f);
    }
    __syncthreads();
    if (tid < 10) {
        float a = bfc[tid];
#pragma unroll
        for (int c = 0; c < 64; c++) a += sx[c] * wfc[tid * 64 + c];
        out[m * 10 + tid] = a;
    }
}

// ---------------------------------------------------------------------------
extern "C" void kernel_launch(void* const* d_in, const int* in_sizes, int n_in,
                              void* d_out, int out_size) {
    const float* x   = (const float*)d_in[0];
    const float* wg1 = (const float*)d_in[1];
    const float* bg1 = (const float*)d_in[2];
    const float* wg2 = (const float*)d_in[3];
    const float* bg2 = (const float*)d_in[4];
    const float* wfc = (const float*)d_in[5];
    const float* bfc = (const float*)d_in[6];
    float* out = (float*)d_out;
    int B = in_sizes[0] / NN;
    if (B > MAXB) B = MAXB;

    build_sort_table_kernel<<<NN, 256>>>();
    dtm_kernel<<<dim3(B, 4), 256>>>(x);
    pairs_kernel<<<B * 4, 256>>>();
    mlp_kernel<<<B, 512>>>(wg1, bg1, wg2, bg2, wfc, bfc, out);
}

// round 5
// speedup vs baseline: 5.0059x; 1.5181x over previous
#include <cuda_runtime.h>

#define NN 784
#define GRID 28
#define MAXB 64
#define MAXD2 1459   // d2 in [0, 27^2+27^2=1458]

// Scratch (device globals — no allocations allowed)
__device__ unsigned short g_sort_idx[NN * NN];   // [i][rank] -> neighbor index
__device__ float g_fvals[2 * MAXB * NN];         // [g][m][i] dtm values
__device__ float g_feats[MAXB * 320];            // landscape features per image

__constant__ int c_dxs[8] = {-1, 1, 0, 0, -1, -1, 1, 1};
__constant__ int c_dys[8] = {0, 0, -1, 1, -1, 1, -1, 1};
__constant__ int c_off[8] = {-28, 28, -1, 1, -29, -27, 27, 29};

// ---------------------------------------------------------------------------
// Kernel A: stable argsort of squared grid distances per point (counting sort)
// ---------------------------------------------------------------------------
__global__ void build_sort_table_kernel() {
    int i = blockIdx.x;
    int xi = i / GRID, yi = i % GRID;
    __shared__ unsigned int hist[MAXD2];
    __shared__ unsigned short d2a[NN];
    __shared__ unsigned int wsum[8];
    int tid = threadIdx.x;
    int lane = tid & 31, warp = tid >> 5;

    for (int t = tid; t < MAXD2; t += 256) hist[t] = 0u;
    __syncthreads();
    for (int j = tid; j < NN; j += 256) {
        int dx = j / GRID - xi, dy = j % GRID - yi;
        int d2 = dx * dx + dy * dy;
        d2a[j] = (unsigned short)d2;
        atomicAdd(&hist[d2], 1u);
    }
    __syncthreads();

    // exclusive scan of hist[0..1458] (6 entries per thread, 256 threads)
    unsigned int lv[6];
    unsigned int s = 0u;
    int base = tid * 6;
#pragma unroll
    for (int c = 0; c < 6; c++) {
        unsigned int v = (base + c < MAXD2) ? hist[base + c] : 0u;
        lv[c] = s;
        s += v;
    }
    unsigned int inc = s;
#pragma unroll
    for (int off = 1; off < 32; off <<= 1) {
        unsigned int t = __shfl_up_sync(0xFFFFFFFFu, inc, off);
        if (lane >= off) inc += t;
    }
    if (lane == 31) wsum[warp] = inc;
    __syncthreads();
    if (tid == 0) {
        unsigned int a = 0u;
        for (int w = 0; w < 8; w++) { unsigned int t = wsum[w]; wsum[w] = a; a += t; }
    }
    __syncthreads();
    unsigned int off0 = wsum[warp] + (inc - s);
    __syncthreads();  // all reads of hist done before overwrite
#pragma unroll
    for (int c = 0; c < 6; c++)
        if (base + c < MAXD2) hist[base + c] = off0 + lv[c];
    __syncthreads();

    // Stable scatter: warps serialized in ascending-j order
    for (int gq = 0; gq < 25; gq++) {
        if (warp == (gq & 7)) {
            int j = gq * 32 + lane;
            bool valid = (j < NN);
            unsigned int key = valid ? (unsigned int)d2a[j] : 0xFFFFu;
            unsigned int mk = __match_any_sync(0xFFFFFFFFu, key);
            int leader = __ffs(mk) - 1;
            int pre = __popc(mk & ((1u << lane) - 1u));
            unsigned int b0 = 0u;
            if (lane == leader && valid) b0 = atomicAdd(&hist[key], (unsigned int)__popc(mk));
            b0 = __shfl_sync(0xFFFFFFFFu, b0, leader);
            if (valid) g_sort_idx[i * NN + b0 + pre] = (unsigned short)j;
        }
        __syncthreads();
    }
}

// ---------------------------------------------------------------------------
// Kernel B: DTM for both m0 values in a single pass. Grid (B, 4): 4 blocks/img.
// ---------------------------------------------------------------------------
__global__ void dtm_kernel(const float* __restrict__ x) {
    int m = blockIdx.x;
    __shared__ float img[NN];
    __shared__ float red[8];
    int tid = threadIdx.x;
    int lane = tid & 31, warp = tid >> 5;

    float ps = 0.f;
    for (int j = tid; j < NN; j += 256) {
        float v = x[m * NN + j];
        img[j] = v;
        ps += v;
    }
#pragma unroll
    for (int off = 16; off; off >>= 1) ps += __shfl_xor_sync(0xFFFFFFFFu, ps, off);
    if (lane == 0) red[warp] = ps;
    __syncthreads();
    float S = 0.f;
#pragma unroll
    for (int w = 0; w < 8; w++) S += red[w];
    float bound1 = 0.05f * S;
    float bound2 = 0.2f * S;

    int wglob = blockIdx.y * 8 + warp;   // 32 warps per image
    for (int i = wglob; i < NN; i += 32) {
        int xi = i / GRID, yi = i % GRID;
        float acc1 = 0.f, acc2 = 0.f, running = 0.f;
        for (int c = 0; c < NN; c += 32) {
            int j = c + lane;
            float w = 0.f, fd2 = 0.f;
            if (j < NN) {
                int idx = (int)g_sort_idx[i * NN + j];
                w = img[idx];
                int dx = idx / GRID - xi, dy = idx % GRID - yi;
                fd2 = (float)(dx * dx + dy * dy);
            }
            float cs = w;
#pragma unroll
            for (int off = 1; off < 32; off <<= 1) {
                float t = __shfl_up_sync(0xFFFFFFFFu, cs, off);
                if (lane >= off) cs += t;
            }
            float cumBefore = running + cs - w;
            float e1 = fminf(fmaxf(bound1 - cumBefore, 0.f), w);
            float e2 = fminf(fmaxf(bound2 - cumBefore, 0.f), w);
            acc1 += e1 * fd2;
            acc2 += e2 * fd2;
            running += __shfl_sync(0xFFFFFFFFu, cs, 31);
            if (running >= bound2) break;  // all further eff are exactly 0
        }
#pragma unroll
        for (int off = 16; off; off >>= 1) {
            acc1 += __shfl_xor_sync(0xFFFFFFFFu, acc1, off);
            acc2 += __shfl_xor_sync(0xFFFFFFFFu, acc2, off);
        }
        if (lane == 0) {
            g_fvals[(0 * MAXB + m) * NN + i] = sqrtf(acc1 / bound1);
            g_fvals[(1 * MAXB + m) * NN + i] = sqrtf(acc2 / bound2);
        }
    }
}

// ---------------------------------------------------------------------------
// Kernel C: per-task stable sort (bitonic) + batched (4-vertex) union-find
// + fused landscape top-K. One launch: task = blockIdx.x = ((m*2+g)*2+dir).
// ---------------------------------------------------------------------------
struct SmemC {
    unsigned long long keys[1024];
    float vals[NN];
    unsigned order32[NN + 4];        // (yj<<24)|(xj<<16)|j per rank
    unsigned par32[NN];              // root: (birth_pos<<16)|root ; else low16=parent
    unsigned short pos_[NN];
    unsigned char nbm[NN];           // per-rank eligible-neighbor bitmask
    float spB[NN], spD[NN];
};

template <int DIR>
__device__ __forceinline__ void pairs_body(SmemC* s, int g, int m) {
    int tid = threadIdx.x;
    int lane = tid & 31, warp = tid >> 5;
    const unsigned EMASK = DIR ? 0xFFu : 0x0Fu;
    const unsigned INV = 0xFFFFFFFFu;

    for (int j = tid; j < NN; j += 256) {
        float v = g_fvals[(g * MAXB + m) * NN + j];
        s->vals[j] = v;
        float kf = DIR ? -v : v;  // dir1: superlevel via -x
        unsigned int u = __float_as_uint(kf);
        u = (u & 0x80000000u) ? ~u : (u | 0x80000000u);  // sortable transform
        s->keys[j] = ((unsigned long long)u << 32) | (unsigned int)j;  // stable ties by j
        s->spB[j] = 0.f;
        s->spD[j] = 0.f;
    }
    for (int j = NN + tid; j < 1024; j += 256) s->keys[j] = ~0ULL;
    __syncthreads();

    // bitonic sort of 1024 keys
    for (int k = 2; k <= 1024; k <<= 1) {
        for (int jj = k >> 1; jj > 0; jj >>= 1) {
            for (int i = tid; i < 1024; i += 256) {
                int ixj = i ^ jj;
                if (ixj > i) {
                    unsigned long long a = s->keys[i], b = s->keys[ixj];
                    bool up = ((i & k) == 0);
                    if ((a > b) == up) { s->keys[i] = b; s->keys[ixj] = a; }
                }
            }
            __syncthreads();
        }
    }

    for (int r = tid; r < NN; r += 256) {
        int j = (int)(unsigned int)s->keys[r];
        int xj = j / GRID, yj = j % GRID;
        s->order32[r] = (unsigned)j | ((unsigned)xj << 16) | ((unsigned)yj << 24);
        s->pos_[j] = (unsigned short)r;
        s->par32[j] = ((unsigned)r << 16) | (unsigned)j;   // root: birth<<16 | self
    }
    if (tid < 4) s->order32[NN + tid] = 0u;
    __syncthreads();

    // precompute per-rank eligible-neighbor bitmask (pos[u] < r, in bounds)
    for (int r = tid; r < NN; r += 256) {
        unsigned o = s->order32[r];
        int v = (int)(o & 0xFFFFu);
        int xv = (int)((o >> 16) & 0xFFu), yv = (int)(o >> 24);
        unsigned mask = 0u;
#pragma unroll
        for (int l = 0; l < 8; l++) {
            int xu = xv + c_dxs[l], yu = yv + c_dys[l];
            if ((unsigned)xu < (unsigned)GRID && (unsigned)yu < (unsigned)GRID &&
                (int)s->pos_[v + c_off[l]] < r)
                mask |= 1u << l;
        }
        s->nbm[r] = (unsigned char)mask;
    }
    __syncthreads();

    // ---- batched union-find: warp 0. 4 vertices per warp step, 8 lanes each.
    // packed = (birth_pos<<16)|root; min packed wins; fresh vertex always loses.
    if (tid < 32) {
        volatile unsigned* par = s->par32;
        int k = 0;
        int sub = lane >> 3, sl = lane & 7;
        unsigned lmlt = (1u << lane) - 1u;
        for (int base = 0; base < NN; base += 4) {
            unsigned o0 = s->order32[base + 0];
            unsigned o1 = s->order32[base + 1];
            unsigned o2 = s->order32[base + 2];
            unsigned o3 = s->order32[base + 3];
            unsigned em = (unsigned)s->nbm[base + sub] & EMASK;
            unsigned ov = (sub < 2) ? (sub == 0 ? o0 : o1) : (sub == 2 ? o2 : o3);
            unsigned pv0 = ((unsigned)(base + 0) << 16) | (o0 & 0xFFFFu);
            unsigned pv1 = ((unsigned)(base + 1) << 16) | (o1 & 0xFFFFu);
            unsigned pv2 = ((unsigned)(base + 2) << 16) | (o2 & 0xFFFFu);
            unsigned pv3 = ((unsigned)(base + 3) << 16) | (o3 & 0xFFFFu);

            // optimistic finds against pre-batch parent state
            unsigned cur = INV;
            if ((em >> sl) & 1u) {
                int xx = (int)(ov & 0xFFFFu) + c_off[sl];
                for (;;) {  // find, 2 levels/iter with path halving
                    unsigned p32 = par[xx];
                    int pl = (int)(p32 & 0xFFFFu);
                    if (pl == xx) { cur = p32; break; }
                    unsigned q32 = par[pl];
                    int ql = (int)(q32 & 0xFFFFu);
                    if (ql == pl) { cur = q32; break; }
                    par[xx] = q32;      // halve: xx -> grandparent
                    xx = ql;
                }
            }

            // resolve subs 0..3 in order, fixing later lanes' stale roots
#pragma unroll
            for (int j = 0; j < 4; j++) {
                unsigned pvj = (j < 2) ? (j == 0 ? pv0 : pv1) : (j == 2 ? pv2 : pv3);
                unsigned grp = __match_any_sync(0xFFFFFFFFu, cur);
                bool inj = (sub == j);
                bool valid = (cur != INV);
                unsigned wj = __reduce_min_sync(0xFFFFFFFFu, (valid && inj) ? cur : INV);
                bool anyv = (wj != INV);
                bool deadval = inj && valid && (cur != wj);
                unsigned dmask = __ballot_sync(0xFFFFFFFFu, deadval);
                bool leader = deadval && ((grp & dmask & lmlt) == 0u);
                unsigned lmask = __ballot_sync(0xFFFFFFFFu, leader);
                unsigned vj = pvj & 0xFFFFu;
                if (leader) {
                    par[cur & 0xFFFFu] = wj;            // point dead root at winner
                    int rk = k + __popc(lmask & lmlt);
                    int lbv = (int)(s->order32[cur >> 16] & 0xFFFFu);
                    float Bv, Dv;
                    if (DIR == 0) { Bv = s->vals[lbv]; Dv = s->vals[vj]; }
                    else          { Bv = s->vals[vj];  Dv = s->vals[lbv]; }
                    s->spB[rk] = Bv;
                    s->spD[rk] = Dv;
                }
                k += __popc(lmask);
                if (anyv && lane == 0) par[vj] = wj;    // fresh vertex joins winner
                // fix stale roots in later subs
                if (sub > j && valid) {
                    bool stale = ((grp & dmask) != 0u) || (anyv && cur == pvj);
                    if (stale) cur = wj;
                }
            }
            __syncwarp();
        }
    }
    __syncthreads();

    // ---- fused landscape top-K: 32 t-values, warp per t ----
    int K = g ? 3 : 2;
    float start = g ? 1.0f : 0.0f;
    int fbase = m * 320 + (g ? 128 : 0);
    for (int ti = warp; ti < 32; ti += 8) {
        float t = start + 7.0f * (float)ti / 31.0f;
        float a0 = -1.f, a1 = -1.f, a2 = -1.f;
        for (int j = lane; j < NN; j += 32) {
            float tent = fmaxf(fminf(t - s->spB[j], s->spD[j] - t), 0.f);
            if (tent > a2) {
                if (tent > a0)      { a2 = a1; a1 = a0; a0 = tent; }
                else if (tent > a1) { a2 = a1; a1 = tent; }
                else                { a2 = tent; }
            }
        }
        for (int kk = 0; kk < K; kk++) {
            float w = a0;
#pragma unroll
            for (int off = 16; off; off >>= 1) w = fmaxf(w, __shfl_xor_sync(0xFFFFFFFFu, w, off));
            unsigned bal = __ballot_sync(0xFFFFFFFFu, a0 == w);
            int src = __ffs(bal) - 1;
            if (lane == src) { a0 = a1; a1 = a2; a2 = -1.f; }
            if (lane == 0) g_feats[fbase + (DIR * K + kk) * 32 + ti] = w;
        }
    }
}

__global__ void pairs_kernel() {
    __shared__ SmemC smc;
    int task = blockIdx.x;
    int dir = task & 1;
    int g = (task >> 1) & 1;
    int m = task >> 2;
    if (dir == 0) pairs_body<0>(&smc, g, m);
    else          pairs_body<1>(&smc, g, m);
}

// ---------------------------------------------------------------------------
// Kernel D: tiny MLP. Block per image, 512 threads, warp-per-unit dots.
// ---------------------------------------------------------------------------
__global__ void mlp_kernel(const float* __restrict__ wg1, const float* __restrict__ bg1,
                           const float* __restrict__ wg2, const float* __restrict__ bg2,
                           const float* __restrict__ wfc, const float* __restrict__ bfc,
                           float* __restrict__ out) {
    int m = blockIdx.x;
    __shared__ float sx[64];
    int tid = threadIdx.x;
    int lane = tid & 31, w = tid >> 5;   // 16 warps
    const float* feats = g_feats + m * 320;

#pragma unroll
    for (int i = 0; i < 2; i++) {
        int u = w * 2 + i;
        float a = 0.f;
#pragma unroll
        for (int c = lane; c < 128; c += 32) a += feats[c] * wg1[u * 128 + c];
#pragma unroll
        for (int off = 16; off; off >>= 1) a += __shfl_xor_sync(0xFFFFFFFFu, a, off);
        if (lane == 0) sx[u] = fmaxf(a + bg1[u], 0.f);
    }
#pragma unroll
    for (int i = 0; i < 2; i++) {
        int u = w * 2 + i;
        float a = 0.f;
#pragma unroll
        for (int c = lane; c < 192; c += 32) a += feats[128 + c] * wg2[u * 192 + c];
#pragma unroll
        for (int off = 16; off; off >>= 1) a += __shfl_xor_sync(0xFFFFFFFFu, a, off);
        if (lane == 0) sx[32 + u] = fmaxf(a + bg2[u], 0.f);
    }
    __syncthreads();
    if (tid < 10) {
        float a = bfc[tid];
#pragma unroll
        for (int c = 0; c < 64; c++) a += sx[c] * wfc[tid * 64 + c];
        out[m * 10 + tid] = a;
    }
}

// ---------------------------------------------------------------------------
extern "C" void kernel_launch(void* const* d_in, const int* in_sizes, int n_in,
                              void* d_out, int out_size) {
    const float* x   = (const float*)d_in[0];
    const float* wg1 = (const float*)d_in[1];
    const float* bg1 = (const float*)d_in[2];
    const float* wg2 = (const float*)d_in[3];
    const float* bg2 = (const float*)d_in[4];
    const float* wfc = (const float*)d_in[5];
    const float* bfc = (const float*)d_in[6];
    float* out = (float*)d_out;
    int B = in_sizes[0] / NN;
    if (B > MAXB) B = MAXB;

    build_sort_table_kernel<<<NN, 256>>>();
    dtm_kernel<<<dim3(B, 4), 256>>>(x);
    pairs_kernel<<<B * 4, 256>>>();
    mlp_kernel<<<B, 512>>>(wg1, bg1, wg2, bg2, wfc, bfc, out);
}